// round 4
// baseline (speedup 1.0000x reference)
#include <cuda_runtime.h>
#include <math.h>

#define Nn 20000
#define Ne 100000
#define FN 26
#define FE 21
#define FEA 22   // edge features + constant-1 slot folding eb
#define H1 64
#define H2 30
#define G4 256   // 4*H1
#define T1ROW (FEA*H1)   // 1408
#define T2ROW (FEA*H2)   // 660

// ------------------------- scratch (device globals) -------------------------
__device__ float g_ewT1[FEA*FN*H1];        // [f][i][o]  (f==21 row holds eb1)
__device__ float g_ewT2[FEA*H1*H2];
__device__ float g_T1[Nn*T1ROW];           // 112.6 MB
__device__ float g_self1[Nn*H1];
__device__ float g_s1[Nn*H1];
__device__ float g_cnt[Nn];
__device__ float g_h1[Nn*H1];
__device__ float g_T2[Nn*T2ROW];           // 52.8 MB
__device__ float g_self2[Nn*H2];
__device__ float g_s2[Nn*H2];
__device__ float g_h2[Nn*H2];
__device__ float g_pre[2][Nn*G4];          // LSTM input projections (fwd/bwd)
__device__ float g_hcat[Nn*2*H1];

// packed f32x2 FMA (Blackwell FFMA2)
__device__ __forceinline__ float2 ffma2(float2 a, float2 b, float2 c) {
    unsigned long long ua = *reinterpret_cast<unsigned long long*>(&a);
    unsigned long long ub = *reinterpret_cast<unsigned long long*>(&b);
    unsigned long long uc = *reinterpret_cast<unsigned long long*>(&c);
    unsigned long long ud;
    asm("fma.rn.f32x2 %0, %1, %2, %3;" : "=l"(ud) : "l"(ua), "l"(ub), "l"(uc));
    return *reinterpret_cast<float2*>(&ud);
}

// ------------------------- weight re-layout -------------------------
__global__ void k_prep(const float* __restrict__ ew1, const float* __restrict__ eb1,
                       const float* __restrict__ ew2, const float* __restrict__ eb2) {
    const int n1 = FEA*FN*H1, n2 = FEA*H1*H2;
    for (int idx = blockIdx.x*blockDim.x + threadIdx.x; idx < n1+n2; idx += gridDim.x*blockDim.x) {
        if (idx < n1) {
            int f = idx / (FN*H1), r = idx % (FN*H1), i = r / H1, o = r % H1;
            g_ewT1[idx] = (f < FE) ? ew1[(i*H1+o)*FE + f] : eb1[i*H1+o];
        } else {
            int j = idx - n1;
            int f = j / (H1*H2), r = j % (H1*H2), i = r / H2, o = r % H2;
            g_ewT2[j] = (f < FE) ? ew2[(i*H2+o)*FE + f] : eb2[i*H2+o];
        }
    }
}

__global__ void k_zero() {
    const int tot = Nn*H1 + Nn*H2 + Nn;
    for (int idx = blockIdx.x*blockDim.x + threadIdx.x; idx < tot; idx += gridDim.x*blockDim.x) {
        if (idx < Nn*H1) g_s1[idx] = 0.f;
        else if (idx < Nn*H1 + Nn*H2) g_s2[idx - Nn*H1] = 0.f;
        else g_cnt[idx - Nn*H1 - Nn*H2] = 0.f;
    }
}

// ------------------------- layer 1: per-node T1 + self term -------------------------
__global__ void k_t1(const float* __restrict__ x, const float* __restrict__ root1,
                     const float* __restrict__ b1) {
    __shared__ float xs[FN];
    int n = blockIdx.x, tid = threadIdx.x;
    if (tid < FN) xs[tid] = x[n*FN + tid];
    __syncthreads();
    for (int idx = tid; idx < T1ROW; idx += blockDim.x) {
        int f = idx >> 6, o = idx & 63;
        const float* w = &g_ewT1[(f*FN)*H1 + o];
        float acc = 0.f;
        #pragma unroll
        for (int i = 0; i < FN; i++) acc += xs[i] * w[i*H1];
        g_T1[n*T1ROW + idx] = acc;
    }
    if (tid < H1) {
        float acc = b1[tid];
        #pragma unroll
        for (int i = 0; i < FN; i++) acc += xs[i] * root1[i*H1 + tid];
        g_self1[n*H1 + tid] = acc;
    }
}

// ------------------------- layer 1: edge contract + scatter -------------------------
__global__ void k_edge1(const int* __restrict__ ei, const float* __restrict__ ea) {
    __shared__ float ea_s[4][FEA];
    int tid = threadIdx.x;
    int slot = tid >> 6, o = tid & 63;
    int e = blockIdx.x*4 + slot;
    if (o < FE) ea_s[slot][o] = ea[e*FE + o];
    else if (o == FE) ea_s[slot][FE] = 1.f;
    __syncthreads();
    int src = ei[e], dst = ei[Ne + e];
    const float* Tp = &g_T1[src*T1ROW + o];
    float acc = 0.f;
    #pragma unroll
    for (int f = 0; f < FEA; f++) acc += ea_s[slot][f] * Tp[f*H1];
    atomicAdd(&g_s1[dst*H1 + o], acc);
    if (o == 0) atomicAdd(&g_cnt[dst], 1.f);
}

// ------------------------- layer 1: mean + root + LN + leaky -------------------------
__global__ void k_node1(const float* __restrict__ g1, const float* __restrict__ be1) {
    int n = blockIdx.x, o = threadIdx.x;
    float cnt = fmaxf(g_cnt[n], 1.f);
    float v = g_s1[n*H1 + o] / cnt + g_self1[n*H1 + o];
    float s = v, q = v*v;
    for (int m = 16; m > 0; m >>= 1) {
        s += __shfl_xor_sync(0xffffffffu, s, m);
        q += __shfl_xor_sync(0xffffffffu, q, m);
    }
    __shared__ float rs[2], rq[2];
    if ((o & 31) == 0) { rs[o>>5] = s; rq[o>>5] = q; }
    __syncthreads();
    float S = rs[0]+rs[1], Q = rq[0]+rq[1];
    float mean = S * (1.f/H1);
    float var  = Q * (1.f/H1) - mean*mean;
    float nv = (v - mean) * rsqrtf(var + 1e-5f) * g1[o] + be1[o];
    g_h1[n*H1 + o] = nv > 0.f ? nv : 0.01f*nv;
}

// ------------------------- layer 2: per-node T2 + self -------------------------
__global__ void k_t2(const float* __restrict__ root2, const float* __restrict__ b2) {
    __shared__ float hs[H1];
    int n = blockIdx.x, tid = threadIdx.x;
    if (tid < H1) hs[tid] = g_h1[n*H1 + tid];
    __syncthreads();
    for (int idx = tid; idx < T2ROW; idx += blockDim.x) {
        int f = idx / H2, o = idx - f*H2;
        const float* w = &g_ewT2[(f*H1)*H2 + o];
        float acc = 0.f;
        #pragma unroll
        for (int i = 0; i < H1; i++) acc += hs[i] * w[i*H2];
        g_T2[n*T2ROW + idx] = acc;
    }
    if (tid < H2) {
        float acc = b2[tid];
        #pragma unroll
        for (int i = 0; i < H1; i++) acc += hs[i] * root2[i*H2 + tid];
        g_self2[n*H2 + tid] = acc;
    }
}

__global__ void k_edge2(const int* __restrict__ ei, const float* __restrict__ ea) {
    __shared__ float ea_s[8][FEA];
    int tid = threadIdx.x;
    int slot = tid >> 5, o = tid & 31;
    int e = blockIdx.x*8 + slot;
    if (o < FE) ea_s[slot][o] = ea[e*FE + o];
    else if (o == FE) ea_s[slot][FE] = 1.f;
    __syncthreads();
    if (o < H2) {
        int src = ei[e], dst = ei[Ne + e];
        const float* Tp = &g_T2[src*T2ROW + o];
        float acc = 0.f;
        #pragma unroll
        for (int f = 0; f < FEA; f++) acc += ea_s[slot][f] * Tp[f*H2];
        atomicAdd(&g_s2[dst*H2 + o], acc);
    }
}

__global__ void k_node2(const float* __restrict__ g2, const float* __restrict__ be2) {
    int n = blockIdx.x, o = threadIdx.x;       // 32 threads, 30 active
    bool act = o < H2;
    float cnt = fmaxf(g_cnt[n], 1.f);
    float v = act ? (g_s2[n*H2 + o] / cnt + g_self2[n*H2 + o]) : 0.f;
    float s = v, q = v*v;
    for (int m = 16; m > 0; m >>= 1) {
        s += __shfl_xor_sync(0xffffffffu, s, m);
        q += __shfl_xor_sync(0xffffffffu, q, m);
    }
    float mean = s * (1.f/H2);
    float var  = q * (1.f/H2) - mean*mean;
    if (act) {
        float nv = (v - mean) * rsqrtf(var + 1e-5f) * g2[o] + be2[o];
        g_h2[n*H2 + o] = nv > 0.f ? nv : 0.01f*nv;
    }
}

// ------------------------- LSTM input projection (batched) -------------------------
__global__ void k_pre(const float* __restrict__ Wih_f, const float* __restrict__ bih_f,
                      const float* __restrict__ bhh_f,
                      const float* __restrict__ Wih_b, const float* __restrict__ bih_b,
                      const float* __restrict__ bhh_b) {
    __shared__ float hv[H2];
    int n = blockIdx.x, g = threadIdx.x;
    if (g < H2) hv[g] = g_h2[n*H2 + g];
    __syncthreads();
    float af = bih_f[g] + bhh_f[g];
    float ab = bih_b[g] + bhh_b[g];
    #pragma unroll
    for (int j = 0; j < H2; j++) {
        af += hv[j] * Wih_f[g*H2 + j];
        ab += hv[j] * Wih_b[g*H2 + j];
    }
    g_pre[0][n*G4 + g] = af;
    g_pre[1][n*G4 + g] = ab;
}

// ------------------------- BiLSTM (2 persistent CTAs) -------------------------
__global__ void __launch_bounds__(G4, 1)
k_lstm(const float* __restrict__ Whh_f, const float* __restrict__ Whh_b) {
    int dir = blockIdx.x;
    int g = threadIdx.x;
    const float* Whh = dir ? Whh_b : Whh_f;
    const float* pre = g_pre[dir];

    // each thread owns one gate row of Whh, packed as float2
    float2 w2[H1/2];
    {
        const float2* wp = reinterpret_cast<const float2*>(&Whh[g*H1]);
        #pragma unroll
        for (int k = 0; k < H1/2; k++) w2[k] = wp[k];
    }

    __shared__ __align__(16) float h_sh[H1];
    __shared__ float gs[G4];
    if (g < H1) h_sh[g] = 0.f;
    float c = 0.f;
    int gt = g >> 6;                    // 0:i 1:f 2:g 3:o
    __syncthreads();

    // depth-2 prefetch of input projections
    auto pidx = [&](int s) { int t = dir ? (Nn-1-s) : s; return t*G4 + g; };
    float p0 = pre[pidx(0)];
    float p1 = pre[pidx(1)];

    for (int s = 0; s < Nn; s++) {
        float acc = p0;
        p0 = p1;
        if (s + 2 < Nn) p1 = __ldg(&pre[pidx(s+2)]);

        float2 a2 = make_float2(acc, 0.f);
        const float4* h4 = reinterpret_cast<const float4*>(h_sh);
        #pragma unroll
        for (int k = 0; k < H1/4; k++) {
            float4 hvv = h4[k];
            a2 = ffma2(w2[2*k],   make_float2(hvv.x, hvv.y), a2);
            a2 = ffma2(w2[2*k+1], make_float2(hvv.z, hvv.w), a2);
        }
        float d = a2.x + a2.y;
        float actv = (gt == 2) ? tanhf(d) : (1.f / (1.f + __expf(-d)));
        gs[g] = actv;
        __syncthreads();
        if (g < H1) {
            float iv = gs[g], fv = gs[H1+g], gv = gs[2*H1+g], ov = gs[3*H1+g];
            c = fv*c + iv*gv;
            float h = ov * tanhf(c);
            h_sh[g] = h;
            int t = dir ? (Nn-1-s) : s;
            g_hcat[t*(2*H1) + dir*H1 + g] = h;
        }
        __syncthreads();
    }
}

// ------------------------- final LN + FC -------------------------
__global__ void k_out(const float* __restrict__ gl, const float* __restrict__ bl,
                      const float* __restrict__ fcw, const float* __restrict__ fcb,
                      float* __restrict__ out) {
    int n = blockIdx.x, j = threadIdx.x;      // 128 threads
    float v = g_hcat[n*128 + j];
    float s = v, q = v*v;
    for (int m = 16; m > 0; m >>= 1) {
        s += __shfl_xor_sync(0xffffffffu, s, m);
        q += __shfl_xor_sync(0xffffffffu, q, m);
    }
    __shared__ float rs[4], rq[4];
    if ((j & 31) == 0) { rs[j>>5] = s; rq[j>>5] = q; }
    __syncthreads();
    float S = rs[0]+rs[1]+rs[2]+rs[3];
    float Q = rq[0]+rq[1]+rq[2]+rq[3];
    float mean = S * (1.f/128.f);
    float var  = Q * (1.f/128.f) - mean*mean;
    float nv = (v - mean) * rsqrtf(var + 1e-5f) * gl[j] + bl[j];
    float p0 = nv * fcw[j];
    float p1 = nv * fcw[128 + j];
    for (int m = 16; m > 0; m >>= 1) {
        p0 += __shfl_xor_sync(0xffffffffu, p0, m);
        p1 += __shfl_xor_sync(0xffffffffu, p1, m);
    }
    __shared__ float r0[4], r1[4];
    if ((j & 31) == 0) { r0[j>>5] = p0; r1[j>>5] = p1; }
    __syncthreads();
    if (j == 0) {
        out[n*2 + 0] = r0[0]+r0[1]+r0[2]+r0[3] + fcb[0];
        out[n*2 + 1] = r1[0]+r1[1]+r1[2]+r1[3] + fcb[1];
    }
}

// ------------------------- launch -------------------------
extern "C" void kernel_launch(void* const* d_in, const int* in_sizes, int n_in,
                              void* d_out, int out_size) {
    const float* x      = (const float*)d_in[0];
    const int*   ei     = (const int*)  d_in[1];
    const float* ea     = (const float*)d_in[2];
    const float* ew1    = (const float*)d_in[3];
    const float* eb1    = (const float*)d_in[4];
    const float* root1  = (const float*)d_in[5];
    const float* b1     = (const float*)d_in[6];
    const float* g1     = (const float*)d_in[7];
    const float* be1    = (const float*)d_in[8];
    const float* ew2    = (const float*)d_in[9];
    const float* eb2    = (const float*)d_in[10];
    const float* root2  = (const float*)d_in[11];
    const float* b2     = (const float*)d_in[12];
    const float* g2     = (const float*)d_in[13];
    const float* be2    = (const float*)d_in[14];
    const float* Wih_f  = (const float*)d_in[15];
    const float* Whh_f  = (const float*)d_in[16];
    const float* bih_f  = (const float*)d_in[17];
    const float* bhh_f  = (const float*)d_in[18];
    const float* Wih_b  = (const float*)d_in[19];
    const float* Whh_b  = (const float*)d_in[20];
    const float* bih_b  = (const float*)d_in[21];
    const float* bhh_b  = (const float*)d_in[22];
    const float* gl     = (const float*)d_in[23];
    const float* bl     = (const float*)d_in[24];
    const float* fcw    = (const float*)d_in[25];
    const float* fcb    = (const float*)d_in[26];
    float* out = (float*)d_out;

    k_prep <<<80, 512>>>(ew1, eb1, ew2, eb2);
    k_zero <<<1024, 512>>>();
    k_t1   <<<Nn, 128>>>(x, root1, b1);
    k_edge1<<<Ne/4, 256>>>(ei, ea);
    k_node1<<<Nn, 64>>>(g1, be1);
    k_t2   <<<Nn, 128>>>(root2, b2);
    k_edge2<<<Ne/8, 256>>>(ei, ea);
    k_node2<<<Nn, 32>>>(g2, be2);
    k_pre  <<<Nn, G4>>>(Wih_f, bih_f, bhh_f, Wih_b, bih_b, bhh_b);
    k_lstm <<<2, G4>>>(Whh_f, Whh_b);
    k_out  <<<Nn, 128>>>(gl, bl, fcw, fcb, out);
}